// round 8
// baseline (speedup 1.0000x reference)
#include <cuda_runtime.h>
#include <math.h>

#define Bn 64
#define Sn 512
#define Hn 1024
#define Ln 9
#define NCH 16
#define CH 32

// Scratch (no allocations allowed)
__device__ float g_em[(size_t)Bn * Sn * Ln];        // emissions, 1.18 MB (L2-resident)
__device__ float g_M[(size_t)Bn * NCH * Ln * Ln];   // per-chunk transfer matrices
__device__ float g_acc;                              // final accumulator: sum(logZ) - sum(score)

__global__ void k_init() { g_acc = 0.f; }

// ---------------------------------------------------------------------------
// Kernel 1: emissions GEMM. warp = 8 rows, 4 lanes (quad) per row, K split
// across quad as float4 strides. W staged in smem, accumulators in registers.
// ---------------------------------------------------------------------------
__global__ void __launch_bounds__(256) k_gemm(const float* __restrict__ x,
                                              const float* __restrict__ W,
                                              const float* __restrict__ bias) {
    __shared__ float sW[Ln * Hn];
    __shared__ float sb[Ln];
    int tid = threadIdx.x;
    for (int i = tid; i < Ln * Hn; i += 256) sW[i] = W[i];
    if (tid < Ln) sb[tid] = bias[tid];
    __syncthreads();

    int lane = tid & 31;
    int warp = tid >> 5;
    int gw = blockIdx.x * 8 + warp;         // 512 blocks * 8 warps = 4096 warps
    int rw = lane >> 2;                      // row within warp: 0..7
    int quad = lane & 3;                     // k-slice within row
    size_t row = (size_t)gw * 8 + rw;        // < 32768 exactly

    const float4* xr = (const float4*)(x + row * Hn);
    float acc[Ln];
#pragma unroll
    for (int l = 0; l < Ln; l++) acc[l] = 0.f;

#pragma unroll 4
    for (int j = 0; j < 64; j++) {
        int kv = quad + j * 4;               // float4 index into the 1024-float row
        float4 xv = xr[kv];
#pragma unroll
        for (int l = 0; l < Ln; l++) {
            float4 wv = ((const float4*)(sW + l * Hn))[kv];
            acc[l] += xv.x * wv.x + xv.y * wv.y + xv.z * wv.z + xv.w * wv.w;
        }
    }
    // reduce across the quad (lanes differing in bits 0,1 share a row)
#pragma unroll
    for (int l = 0; l < Ln; l++) {
        acc[l] += __shfl_xor_sync(0xffffffffu, acc[l], 1);
        acc[l] += __shfl_xor_sync(0xffffffffu, acc[l], 2);
    }
    if (quad == 0) {
        float* o = g_em + row * Ln;
#pragma unroll
        for (int l = 0; l < Ln; l++) o[l] = acc[l] + sb[l];
    }
}

// ---------------------------------------------------------------------------
// Kernel 2: numerator score. One block per batch, thread per timestep.
// Accumulates -(score_b) into g_acc.  Mask is int32 (bool marshaled as i32).
// ---------------------------------------------------------------------------
__global__ void __launch_bounds__(512) k_score(const int* __restrict__ tags,
                                               const int* __restrict__ mask,
                                               const float* __restrict__ startT,
                                               const float* __restrict__ endT,
                                               const float* __restrict__ T) {
    __shared__ float sred[16];
    __shared__ int scnt[16];
    int b = blockIdx.x, s = threadIdx.x;
    int lane = s & 31, w = s >> 5;

    int t = tags[b * Sn + s];
    int mk = (mask[b * Sn + s] != 0) ? 1 : 0;
    float term;
    if (s == 0) {
        term = startT[t] + g_em[(size_t)b * Sn * Ln + t];
    } else {
        int tp = tags[b * Sn + s - 1];
        term = mk ? (T[tp * Ln + t] + g_em[((size_t)b * Sn + s) * Ln + t]) : 0.f;
    }
#pragma unroll
    for (int o = 16; o > 0; o >>= 1) {
        term += __shfl_down_sync(0xffffffffu, term, o);
        mk   += __shfl_down_sync(0xffffffffu, mk, o);
    }
    if (lane == 0) { sred[w] = term; scnt[w] = mk; }
    __syncthreads();
    if (w == 0) {
        float tt = (lane < 16) ? sred[lane] : 0.f;
        int   cc = (lane < 16) ? scnt[lane] : 0;
#pragma unroll
        for (int o = 8; o > 0; o >>= 1) {
            tt += __shfl_down_sync(0xffffffffu, tt, o);
            cc += __shfl_down_sync(0xffffffffu, cc, o);
        }
        if (lane == 0) {
            int last = tags[b * Sn + cc - 1];   // seq_end = sum(mask)-1
            atomicAdd(&g_acc, -(tt + endT[last]));
        }
    }
}

// ---------------------------------------------------------------------------
// Kernel 3 (phase A): per (batch, chunk) warp folds 32 timesteps into a 9x9
// log-semiring transfer matrix. M'[i,j] = lse_k(M[i,k] + T[k,j]) + em[s][j].
// Each lane owns entries {lane, lane+32, lane+64}. T columns cached in regs
// (only compile-time indexed, so they stay register-resident).
// ---------------------------------------------------------------------------
__device__ __forceinline__ float lse9(const float* Mrow, const float* Tc) {
    float xv[9], m = -1e30f;
#pragma unroll
    for (int k = 0; k < 9; k++) { xv[k] = Mrow[k] + Tc[k]; m = fmaxf(m, xv[k]); }
    float su = 0.f;
#pragma unroll
    for (int k = 0; k < 9; k++) su += __expf(xv[k] - m);
    return m + __logf(su);
}

__global__ void __launch_bounds__(128) k_chunk(const int* __restrict__ mask,
                                               const float* __restrict__ T) {
    __shared__ float sM[4][81];
    int lane = threadIdx.x & 31, warp = threadIdx.x >> 5;
    int gw = blockIdx.x * 4 + warp;      // 256 blocks * 4 warps = 1024
    int b = gw >> 4, c = gw & 15;
    float* M = sM[warp];

    int e0 = lane, e1 = lane + 32, e2 = lane + 64;
    bool act2 = (e2 < 81);
    int i0 = e0 / 9, j0 = e0 % 9;
    int i1 = e1 / 9, j1 = e1 % 9;
    int i2 = act2 ? e2 / 9 : 0, j2 = act2 ? e2 % 9 : 0;

    float T0[9], T1[9], T2[9];           // Tc[k] = T[k][j] (column j)
#pragma unroll
    for (int k = 0; k < 9; k++) {
        T0[k] = T[k * 9 + j0];
        T1[k] = T[k * 9 + j1];
        T2[k] = act2 ? T[k * 9 + j2] : 0.f;
    }
    // direct loads for the first-step write (avoid runtime-indexing T0/T1/T2)
    float Td0 = T[i0 * 9 + j0];
    float Td1 = T[i1 * 9 + j1];
    float Td2 = act2 ? T[i2 * 9 + j2] : 0.f;

    const float* emb = g_em + (size_t)b * Sn * Ln;
    const int* mb = mask + b * Sn;
    int sb0 = 1 + c * CH;
    int se  = min(Sn, sb0 + CH);

    bool have = false;
    for (int s = sb0; s < se; s++) {
        if (mb[s] == 0) continue;        // uniform per warp
        float e_0 = emb[s * 9 + j0];
        float e_1 = emb[s * 9 + j1];
        float e_2 = act2 ? emb[s * 9 + j2] : 0.f;
        if (!have) {
            M[e0] = Td0 + e_0;           // A_s[i,j] = T[i,j] + em[s][j]
            M[e1] = Td1 + e_1;
            if (act2) M[e2] = Td2 + e_2;
            have = true;
            __syncwarp();
        } else {
            float r0 = lse9(M + i0 * 9, T0) + e_0;
            float r1 = lse9(M + i1 * 9, T1) + e_1;
            float r2 = act2 ? (lse9(M + i2 * 9, T2) + e_2) : 0.f;
            __syncwarp();                // all reads done before writes
            M[e0] = r0; M[e1] = r1; if (act2) M[e2] = r2;
            __syncwarp();
        }
    }

    float* out = g_M + ((size_t)b * NCH + c) * 81;
    if (have) {
        out[e0] = M[e0]; out[e1] = M[e1]; if (act2) out[e2] = M[e2];
    } else {                             // log-identity (chunk fully masked out)
        out[e0] = (i0 == j0) ? 0.f : -1e30f;
        out[e1] = (i1 == j1) ? 0.f : -1e30f;
        if (act2) out[e2] = (i2 == j2) ? 0.f : -1e30f;
    }
}

// ---------------------------------------------------------------------------
// Kernel 4 (phase B): per-batch warp combines alpha0 through the 16 chunk
// matrices, then logZ = lse(v + end). Accumulates +logZ into g_acc.
// ---------------------------------------------------------------------------
__global__ void __launch_bounds__(32) k_phaseB(const float* __restrict__ startT,
                                               const float* __restrict__ endT) {
    __shared__ float sM[NCH * 81];
    int b = blockIdx.x, lane = threadIdx.x;
    const float* gm = g_M + (size_t)b * NCH * 81;
    for (int i = lane; i < NCH * 81; i += 32) sM[i] = gm[i];
    __syncwarp();

    const float* emb = g_em + (size_t)b * Sn * Ln;
    float v[9];                          // alpha, replicated across lanes
#pragma unroll
    for (int j = 0; j < 9; j++) v[j] = startT[j] + emb[j];

    for (int c = 0; c < NCH; c++) {
        float nv = 0.f;
        if (lane < 9) {
            float xv[9], m = -1e30f;
#pragma unroll
            for (int i = 0; i < 9; i++) {
                xv[i] = v[i] + sM[c * 81 + i * 9 + lane];
                m = fmaxf(m, xv[i]);
            }
            float su = 0.f;
#pragma unroll
            for (int i = 0; i < 9; i++) su += __expf(xv[i] - m);
            nv = m + __logf(su);
        }
        __syncwarp();
#pragma unroll
        for (int j = 0; j < 9; j++) v[j] = __shfl_sync(0xffffffffu, nv, j);
    }

    float mz = -1e30f;
#pragma unroll
    for (int j = 0; j < 9; j++) mz = fmaxf(mz, v[j] + endT[j]);
    float su = 0.f;
#pragma unroll
    for (int j = 0; j < 9; j++) su += __expf(v[j] + endT[j] - mz);
    if (lane == 0) atomicAdd(&g_acc, mz + __logf(su));
}

__global__ void k_out(float* __restrict__ out) { out[0] = g_acc; }

// ---------------------------------------------------------------------------
extern "C" void kernel_launch(void* const* d_in, const int* in_sizes, int n_in,
                              void* d_out, int out_size) {
    const float* x      = (const float*)d_in[0];   // (64,512,1024) f32
    const int*   tags   = (const int*)d_in[1];     // (64,512) i32
    const int*   mask   = (const int*)d_in[2];     // (64,512) bool -> marshaled i32
    const float* W      = (const float*)d_in[3];   // (9,1024) f32
    const float* bias   = (const float*)d_in[4];   // (9,)
    const float* startT = (const float*)d_in[5];   // (9,)
    const float* endT   = (const float*)d_in[6];   // (9,)
    const float* T      = (const float*)d_in[7];   // (9,9)

    k_init  <<<1, 1>>>();
    k_gemm  <<<512, 256>>>(x, W, bias);
    k_score <<<64, 512>>>(tags, mask, startT, endT, T);
    k_chunk <<<256, 128>>>(mask, T);
    k_phaseB<<<64, 32>>>(startT, endT);
    k_out   <<<1, 1>>>((float*)d_out);
}

// round 11
// speedup vs baseline: 1.1844x; 1.1844x over previous
#include <cuda_runtime.h>
#include <math.h>

#define Bn 64
#define Sn 512
#define Hn 1024
#define Ln 9
#define NCH 32
#define CH 16

// Scratch (no allocations allowed)
__device__ float g_em[(size_t)Bn * Sn * Ln];        // emissions (log domain), 1.18 MB
__device__ float g_M[(size_t)Bn * NCH * Ln * Ln];   // per-chunk transfer matrices (EXP domain)
__device__ float g_acc;                              // sum(logZ) - sum(score)

#define FMA2(acc, a, b) asm("fma.rn.f32x2 %0, %1, %2, %0;" : "+l"(acc) : "l"(a), "l"(b))

// ---------------------------------------------------------------------------
// Kernel 1: emissions GEMM. Block = 128 thr (4 warps). Warp: 8 row-slots x
// 4-lane quads; each lane accumulates R=4 rows, reusing each W float4 across
// the 4 rows (4x less LDS) with packed f32x2 FMA (2x fewer FMA instrs).
// Block covers 128 rows; grid = 256. Also resets g_acc (stream-ordered).
// ---------------------------------------------------------------------------
__global__ void __launch_bounds__(128) k_gemm(const float* __restrict__ x,
                                              const float* __restrict__ W,
                                              const float* __restrict__ bias) {
    __shared__ float sW[Ln * Hn];
    __shared__ float sb[Ln];
    int tid = threadIdx.x;
    if (blockIdx.x == 0 && tid == 0) g_acc = 0.f;
    for (int i = tid; i < Ln * Hn / 4; i += 128)
        ((float4*)sW)[i] = ((const float4*)W)[i];
    if (tid < Ln) sb[tid] = bias[tid];
    __syncthreads();

    int lane = tid & 31;
    int warp = tid >> 5;
    int rw = lane >> 2;                      // row slot 0..7
    int quad = lane & 3;                     // k-slice
    size_t row0 = (size_t)blockIdx.x * 128 + warp * 32 + rw * 4;

    const ulonglong2* xr = (const ulonglong2*)(x + row0 * Hn);  // 256 u2 per row

    unsigned long long acc[4][Ln];
#pragma unroll
    for (int r = 0; r < 4; r++)
#pragma unroll
        for (int l = 0; l < Ln; l++) acc[r][l] = 0ull;

#pragma unroll 2
    for (int j = 0; j < 64; j++) {
        int kv = quad + j * 4;               // float4 index 0..255
        ulonglong2 x0 = xr[kv];
        ulonglong2 x1 = xr[256 + kv];
        ulonglong2 x2 = xr[512 + kv];
        ulonglong2 x3 = xr[768 + kv];
#pragma unroll
        for (int l = 0; l < Ln; l++) {
            ulonglong2 wv = ((const ulonglong2*)(sW + l * Hn))[kv];
            FMA2(acc[0][l], x0.x, wv.x); FMA2(acc[0][l], x0.y, wv.y);
            FMA2(acc[1][l], x1.x, wv.x); FMA2(acc[1][l], x1.y, wv.y);
            FMA2(acc[2][l], x2.x, wv.x); FMA2(acc[2][l], x2.y, wv.y);
            FMA2(acc[3][l], x3.x, wv.x); FMA2(acc[3][l], x3.y, wv.y);
        }
    }

#pragma unroll
    for (int r = 0; r < 4; r++) {
#pragma unroll
        for (int l = 0; l < Ln; l++) {
            float lo, hi;
            asm("mov.b64 {%0, %1}, %2;" : "=f"(lo), "=f"(hi) : "l"(acc[r][l]));
            float v = lo + hi;
            v += __shfl_xor_sync(0xffffffffu, v, 1);
            v += __shfl_xor_sync(0xffffffffu, v, 2);
            if (quad == 0) g_em[(row0 + r) * Ln + l] = v + sb[l];
        }
    }
}

// ---------------------------------------------------------------------------
// Kernel 2: numerator score. One block per batch, thread per timestep.
// ---------------------------------------------------------------------------
__global__ void __launch_bounds__(512) k_score(const int* __restrict__ tags,
                                               const int* __restrict__ mask,
                                               const float* __restrict__ startT,
                                               const float* __restrict__ endT,
                                               const float* __restrict__ T) {
    __shared__ float sred[16];
    __shared__ int scnt[16];
    int b = blockIdx.x, s = threadIdx.x;
    int lane = s & 31, w = s >> 5;

    int t = tags[b * Sn + s];
    int mk = (mask[b * Sn + s] != 0) ? 1 : 0;
    float term;
    if (s == 0) {
        term = startT[t] + g_em[(size_t)b * Sn * Ln + t];
    } else {
        int tp = tags[b * Sn + s - 1];
        term = mk ? (T[tp * Ln + t] + g_em[((size_t)b * Sn + s) * Ln + t]) : 0.f;
    }
#pragma unroll
    for (int o = 16; o > 0; o >>= 1) {
        term += __shfl_down_sync(0xffffffffu, term, o);
        mk   += __shfl_down_sync(0xffffffffu, mk, o);
    }
    if (lane == 0) { sred[w] = term; scnt[w] = mk; }
    __syncthreads();
    if (w == 0) {
        float tt = (lane < 16) ? sred[lane] : 0.f;
        int   cc = (lane < 16) ? scnt[lane] : 0;
#pragma unroll
        for (int o = 8; o > 0; o >>= 1) {
            tt += __shfl_down_sync(0xffffffffu, tt, o);
            cc += __shfl_down_sync(0xffffffffu, cc, o);
        }
        if (lane == 0) {
            int last = tags[b * Sn + cc - 1];
            atomicAdd(&g_acc, -(tt + endT[last]));
        }
    }
}

// ---------------------------------------------------------------------------
// Kernel 3 (phase A): per (batch, chunk) warp folds CH=16 timesteps into a
// 9x9 transfer matrix in the EXP domain:
//   E'[i,j] = (sum_k E[i,k] * eT[k,j]) * exp(em[s][j])
// With 16 steps the log-magnitude stays < ~55 << 88 -> no fp32 overflow.
// Lane owns entries {lane, lane+32, lane+64}; eT columns in registers;
// ping-pong shared buffers -> one syncwarp per step. Output stays exp-domain.
// ---------------------------------------------------------------------------
__global__ void __launch_bounds__(128) k_chunk(const int* __restrict__ mask,
                                               const float* __restrict__ T) {
    __shared__ float sE[4][2][81];
    int lane = threadIdx.x & 31, warp = threadIdx.x >> 5;
    int gw = blockIdx.x * 4 + warp;      // 512 blocks * 4 = 2048 warps
    int b = gw >> 5, c = gw & 31;

    int e0 = lane, e1 = lane + 32, e2 = lane + 64;
    bool act2 = (e2 < 81);
    int i0 = e0 / 9, j0 = e0 % 9;
    int i1 = e1 / 9, j1 = e1 % 9;
    int i2 = act2 ? e2 / 9 : 0, j2 = act2 ? e2 % 9 : 0;

    float eT0[9], eT1[9], eT2[9];        // exp(T[k][j]) columns
#pragma unroll
    for (int k = 0; k < 9; k++) {
        eT0[k] = __expf(T[k * 9 + j0]);
        eT1[k] = __expf(T[k * 9 + j1]);
        eT2[k] = act2 ? __expf(T[k * 9 + j2]) : 0.f;
    }
    float eTd0 = __expf(T[i0 * 9 + j0]);
    float eTd1 = __expf(T[i1 * 9 + j1]);
    float eTd2 = act2 ? __expf(T[i2 * 9 + j2]) : 0.f;

    const float* emb = g_em + (size_t)b * Sn * Ln;
    const int* mb = mask + b * Sn;
    int s0 = 1 + c * CH;
    int se = min(Sn, s0 + CH);

    // prefetch pipeline for mask + emissions
    int mnext = mb[s0];
    float q0 = emb[s0 * 9 + j0];
    float q1 = emb[s0 * 9 + j1];
    float q2 = act2 ? emb[s0 * 9 + j2] : 0.f;

    int cur = 0;
    bool have = false;
    for (int s = s0; s < se; s++) {
        int mcur = mnext;
        float a0 = q0, a1 = q1, a2 = q2;
        if (s + 1 < se) {
            mnext = mb[s + 1];
            q0 = emb[(s + 1) * 9 + j0];
            q1 = emb[(s + 1) * 9 + j1];
            q2 = act2 ? emb[(s + 1) * 9 + j2] : 0.f;
        }
        if (mcur == 0) continue;         // uniform per warp
        float x0 = __expf(a0);
        float x1 = __expf(a1);
        float x2 = act2 ? __expf(a2) : 0.f;
        if (!have) {
            float* E = sE[warp][cur];
            E[e0] = eTd0 * x0;           // A_s[i,j] = exp(T[i,j]) * exp(em[s][j])
            E[e1] = eTd1 * x1;
            if (act2) E[e2] = eTd2 * x2;
            have = true;
            __syncwarp();
        } else {
            const float* E = sE[warp][cur];
            float* En = sE[warp][cur ^ 1];
            float r0 = 0.f, r1 = 0.f, r2 = 0.f;
#pragma unroll
            for (int k = 0; k < 9; k++) {
                r0 += E[i0 * 9 + k] * eT0[k];
                r1 += E[i1 * 9 + k] * eT1[k];
                if (act2) r2 += E[i2 * 9 + k] * eT2[k];
            }
            En[e0] = r0 * x0;
            En[e1] = r1 * x1;
            if (act2) En[e2] = r2 * x2;
            cur ^= 1;
            __syncwarp();
        }
    }

    float* out = g_M + ((size_t)b * NCH + c) * 81;
    if (have) {
        const float* E = sE[warp][cur];
        out[e0] = E[e0]; out[e1] = E[e1]; if (act2) out[e2] = E[e2];
    } else {                             // exact identity (chunk fully masked)
        out[e0] = (i0 == j0) ? 1.f : 0.f;
        out[e1] = (i1 == j1) ? 1.f : 0.f;
        if (act2) out[e2] = (i2 == j2) ? 1.f : 0.f;
    }
}

// ---------------------------------------------------------------------------
// Kernel 4 (phase B): per-batch warp folds alpha0 through the 32 exp-domain
// chunk matrices with per-step max renormalization; log offset accumulated.
// ---------------------------------------------------------------------------
__global__ void __launch_bounds__(32) k_phaseB(const float* __restrict__ startT,
                                               const float* __restrict__ endT) {
    __shared__ float sE[NCH * 81];       // 10368 B
    int b = blockIdx.x, lane = threadIdx.x;
    const float* gm = g_M + (size_t)b * NCH * 81;
    for (int i = lane; i < NCH * 81; i += 32) sE[i] = gm[i];
    __syncwarp();

    const float* emb = g_em + (size_t)b * Sn * Ln;
    float v[9];                          // linear alpha, replicated per lane
#pragma unroll
    for (int j = 0; j < 9; j++) v[j] = __expf(startT[j] + emb[j]);

    float logoff = 0.f;
    for (int c = 0; c < NCH; c++) {
        float w = 0.f;
        if (lane < 9) {
#pragma unroll
            for (int i = 0; i < 9; i++) w += v[i] * sE[c * 81 + i * 9 + lane];
        }
        float m = w;                     // lanes >= 9 contribute 0 (w >= 0)
        m = fmaxf(m, __shfl_xor_sync(0xffffffffu, m, 1));
        m = fmaxf(m, __shfl_xor_sync(0xffffffffu, m, 2));
        m = fmaxf(m, __shfl_xor_sync(0xffffffffu, m, 4));
        m = fmaxf(m, __shfl_xor_sync(0xffffffffu, m, 8));
        m = fmaxf(m, __shfl_xor_sync(0xffffffffu, m, 16));
        m = fmaxf(m, 1e-30f);
        logoff += __logf(m);
        float nv = w / m;
#pragma unroll
        for (int j = 0; j < 9; j++) v[j] = __shfl_sync(0xffffffffu, nv, j);
    }

    float z = 0.f;
#pragma unroll
    for (int j = 0; j < 9; j++) z += v[j] * __expf(endT[j]);
    if (lane == 0) atomicAdd(&g_acc, logoff + __logf(z));
}

__global__ void k_out(float* __restrict__ out) { out[0] = g_acc; }

// ---------------------------------------------------------------------------
extern "C" void kernel_launch(void* const* d_in, const int* in_sizes, int n_in,
                              void* d_out, int out_size) {
    const float* x      = (const float*)d_in[0];   // (64,512,1024) f32
    const int*   tags   = (const int*)d_in[1];     // (64,512) i32
    const int*   mask   = (const int*)d_in[2];     // (64,512) bool -> i32
    const float* W      = (const float*)d_in[3];   // (9,1024) f32
    const float* bias   = (const float*)d_in[4];   // (9,)
    const float* startT = (const float*)d_in[5];   // (9,)
    const float* endT   = (const float*)d_in[6];   // (9,)
    const float* T      = (const float*)d_in[7];   // (9,9)

    k_gemm  <<<256, 128>>>(x, W, bias);
    k_score <<<64, 512>>>(tags, mask, startT, endT, T);
    k_chunk <<<512, 128>>>(mask, T);
    k_phaseB<<<64, 32>>>(startT, endT);
    k_out   <<<1, 1>>>((float*)d_out);
}

// round 12
// speedup vs baseline: 1.4108x; 1.1912x over previous
#include <cuda_runtime.h>
#include <math.h>

#define Bn 64
#define Sn 512
#define Hn 1024
#define Ln 9
#define NCH 32
#define CH 16

// Scratch (no allocations allowed)
__device__ float g_em[(size_t)Bn * Sn * Ln];        // emissions (log domain), 1.18 MB
__device__ float g_M[(size_t)Bn * NCH * Ln * Ln];   // chunk matrices (EXP domain, max-normalized)
__device__ float g_logs[Bn * NCH];                  // log of each chunk's max entry
__device__ float g_acc;                              // sum(logZ) - sum(score)

#define FMA2(acc, a, b) asm("fma.rn.f32x2 %0, %1, %2, %0;" : "+l"(acc) : "l"(a), "l"(b))

// ---------------------------------------------------------------------------
// Kernel 1: emissions GEMM. 128 blocks x 256 thr (single wave on 148 SMs).
// Warp: 8 row-slots x 4-lane quads; each lane accumulates 4 rows, reusing
// each W float4 across rows (4x less LDS) with packed f32x2 FMA.
// ---------------------------------------------------------------------------
__global__ void __launch_bounds__(256) k_gemm(const float* __restrict__ x,
                                              const float* __restrict__ W,
                                              const float* __restrict__ bias) {
    __shared__ float sW[Ln * Hn];
    __shared__ float sb[Ln];
    int tid = threadIdx.x;
    if (blockIdx.x == 0 && tid == 0) g_acc = 0.f;
    for (int i = tid; i < Ln * Hn / 4; i += 256)
        ((float4*)sW)[i] = ((const float4*)W)[i];
    if (tid < Ln) sb[tid] = bias[tid];
    __syncthreads();

    int lane = tid & 31;
    int warp = tid >> 5;                     // 0..7
    int rw = lane >> 2;                      // row slot 0..7
    int quad = lane & 3;                     // k-slice
    size_t row0 = (size_t)blockIdx.x * 256 + warp * 32 + rw * 4;

    const ulonglong2* xr = (const ulonglong2*)(x + row0 * Hn);  // 256 u2 per row

    unsigned long long acc[4][Ln];
#pragma unroll
    for (int r = 0; r < 4; r++)
#pragma unroll
        for (int l = 0; l < Ln; l++) acc[r][l] = 0ull;

#pragma unroll 2
    for (int j = 0; j < 64; j++) {
        int kv = quad + j * 4;               // float4 index 0..255
        ulonglong2 x0 = xr[kv];
        ulonglong2 x1 = xr[256 + kv];
        ulonglong2 x2 = xr[512 + kv];
        ulonglong2 x3 = xr[768 + kv];
#pragma unroll
        for (int l = 0; l < Ln; l++) {
            ulonglong2 wv = ((const ulonglong2*)(sW + l * Hn))[kv];
            FMA2(acc[0][l], x0.x, wv.x); FMA2(acc[0][l], x0.y, wv.y);
            FMA2(acc[1][l], x1.x, wv.x); FMA2(acc[1][l], x1.y, wv.y);
            FMA2(acc[2][l], x2.x, wv.x); FMA2(acc[2][l], x2.y, wv.y);
            FMA2(acc[3][l], x3.x, wv.x); FMA2(acc[3][l], x3.y, wv.y);
        }
    }

#pragma unroll
    for (int r = 0; r < 4; r++) {
#pragma unroll
        for (int l = 0; l < Ln; l++) {
            float lo, hi;
            asm("mov.b64 {%0, %1}, %2;" : "=f"(lo), "=f"(hi) : "l"(acc[r][l]));
            float v = lo + hi;
            v += __shfl_xor_sync(0xffffffffu, v, 1);
            v += __shfl_xor_sync(0xffffffffu, v, 2);
            if (quad == 0) g_em[(row0 + r) * Ln + l] = v + sb[l];
        }
    }
}

// ---------------------------------------------------------------------------
// Kernel 2: numerator score. One block per batch, thread per timestep.
// ---------------------------------------------------------------------------
__global__ void __launch_bounds__(512) k_score(const int* __restrict__ tags,
                                               const int* __restrict__ mask,
                                               const float* __restrict__ startT,
                                               const float* __restrict__ endT,
                                               const float* __restrict__ T) {
    __shared__ float sred[16];
    __shared__ int scnt[16];
    int b = blockIdx.x, s = threadIdx.x;
    int lane = s & 31, w = s >> 5;

    int t = tags[b * Sn + s];
    int mk = (mask[b * Sn + s] != 0) ? 1 : 0;
    float term;
    if (s == 0) {
        term = startT[t] + g_em[(size_t)b * Sn * Ln + t];
    } else {
        int tp = tags[b * Sn + s - 1];
        term = mk ? (T[tp * Ln + t] + g_em[((size_t)b * Sn + s) * Ln + t]) : 0.f;
    }
#pragma unroll
    for (int o = 16; o > 0; o >>= 1) {
        term += __shfl_down_sync(0xffffffffu, term, o);
        mk   += __shfl_down_sync(0xffffffffu, mk, o);
    }
    if (lane == 0) { sred[w] = term; scnt[w] = mk; }
    __syncthreads();
    if (w == 0) {
        float tt = (lane < 16) ? sred[lane] : 0.f;
        int   cc = (lane < 16) ? scnt[lane] : 0;
#pragma unroll
        for (int o = 8; o > 0; o >>= 1) {
            tt += __shfl_down_sync(0xffffffffu, tt, o);
            cc += __shfl_down_sync(0xffffffffu, cc, o);
        }
        if (lane == 0) {
            int last = tags[b * Sn + cc - 1];
            atomicAdd(&g_acc, -(tt + endT[last]));
        }
    }
}

// ---------------------------------------------------------------------------
// Kernel 3 (phase A): per (batch, chunk) warp folds CH=16 timesteps into a
// 9x9 transfer matrix in the EXP domain:
//   E'[i,j] = (sum_k E[i,k] * eT[k,j]) * exp(em[s][j])
// Output is max-NORMALIZED (max entry = 1); log(max) stored in g_logs so
// phase B can tree-combine without per-product max reductions.
// ---------------------------------------------------------------------------
__global__ void __launch_bounds__(128) k_chunk(const int* __restrict__ mask,
                                               const float* __restrict__ T) {
    __shared__ float sE[4][2][81];
    int lane = threadIdx.x & 31, warp = threadIdx.x >> 5;
    int gw = blockIdx.x * 4 + warp;      // 512 blocks * 4 = 2048 warps
    int b = gw >> 5, c = gw & 31;

    int e0 = lane, e1 = lane + 32, e2 = lane + 64;
    bool act2 = (e2 < 81);
    int i0 = e0 / 9, j0 = e0 % 9;
    int i1 = e1 / 9, j1 = e1 % 9;
    int i2 = act2 ? e2 / 9 : 0, j2 = act2 ? e2 % 9 : 0;

    float eT0[9], eT1[9], eT2[9];        // exp(T[k][j]) columns
#pragma unroll
    for (int k = 0; k < 9; k++) {
        eT0[k] = __expf(T[k * 9 + j0]);
        eT1[k] = __expf(T[k * 9 + j1]);
        eT2[k] = act2 ? __expf(T[k * 9 + j2]) : 0.f;
    }
    float eTd0 = __expf(T[i0 * 9 + j0]);
    float eTd1 = __expf(T[i1 * 9 + j1]);
    float eTd2 = act2 ? __expf(T[i2 * 9 + j2]) : 0.f;

    const float* emb = g_em + (size_t)b * Sn * Ln;
    const int* mb = mask + b * Sn;
    int s0 = 1 + c * CH;
    int se = min(Sn, s0 + CH);

    // prefetch pipeline for mask + emissions
    int mnext = mb[s0];
    float q0 = emb[s0 * 9 + j0];
    float q1 = emb[s0 * 9 + j1];
    float q2 = act2 ? emb[s0 * 9 + j2] : 0.f;

    int cur = 0;
    bool have = false;
    for (int s = s0; s < se; s++) {
        int mcur = mnext;
        float a0 = q0, a1 = q1, a2 = q2;
        if (s + 1 < se) {
            mnext = mb[s + 1];
            q0 = emb[(s + 1) * 9 + j0];
            q1 = emb[(s + 1) * 9 + j1];
            q2 = act2 ? emb[(s + 1) * 9 + j2] : 0.f;
        }
        if (mcur == 0) continue;         // uniform per warp
        float x0 = __expf(a0);
        float x1 = __expf(a1);
        float x2 = act2 ? __expf(a2) : 0.f;
        if (!have) {
            float* E = sE[warp][cur];
            E[e0] = eTd0 * x0;           // A_s[i,j] = exp(T[i,j]) * exp(em[s][j])
            E[e1] = eTd1 * x1;
            if (act2) E[e2] = eTd2 * x2;
            have = true;
            __syncwarp();
        } else {
            const float* E = sE[warp][cur];
            float* En = sE[warp][cur ^ 1];
            float r0 = 0.f, r1 = 0.f, r2 = 0.f;
#pragma unroll
            for (int k = 0; k < 9; k++) {
                r0 += E[i0 * 9 + k] * eT0[k];
                r1 += E[i1 * 9 + k] * eT1[k];
                if (act2) r2 += E[i2 * 9 + k] * eT2[k];
            }
            En[e0] = r0 * x0;
            En[e1] = r1 * x1;
            if (act2) En[e2] = r2 * x2;
            cur ^= 1;
            __syncwarp();
        }
    }

    float* out = g_M + ((size_t)b * NCH + c) * 81;
    if (have) {
        const float* E = sE[warp][cur];
        float v0 = E[e0], v1 = E[e1], v2 = act2 ? E[e2] : 0.f;
        float m = fmaxf(fmaxf(v0, v1), v2);
        m = fmaxf(m, __shfl_xor_sync(0xffffffffu, m, 1));
        m = fmaxf(m, __shfl_xor_sync(0xffffffffu, m, 2));
        m = fmaxf(m, __shfl_xor_sync(0xffffffffu, m, 4));
        m = fmaxf(m, __shfl_xor_sync(0xffffffffu, m, 8));
        m = fmaxf(m, __shfl_xor_sync(0xffffffffu, m, 16));
        m = fmaxf(m, 1e-35f);
        float rcp = 1.f / m;
        out[e0] = v0 * rcp; out[e1] = v1 * rcp; if (act2) out[e2] = v2 * rcp;
        if (lane == 0) g_logs[b * NCH + c] = __logf(m);
    } else {                             // exact identity (chunk fully masked)
        out[e0] = (i0 == j0) ? 1.f : 0.f;
        out[e1] = (i1 == j1) ? 1.f : 0.f;
        if (act2) out[e2] = (i2 == j2) ? 1.f : 0.f;
        if (lane == 0) g_logs[b * NCH + c] = 0.f;
    }
}

// ---------------------------------------------------------------------------
// Kernel 4 (phase B): per-batch BLOCK tree-combines the 32 normalized chunk
// matrices (5 levels, 31 matrix products, each scaled by 1/9 so entries stay
// <= 1 without any max search), then logZ = log(a0^T F e^end) + 31*ln9 + sum(logs).
// ---------------------------------------------------------------------------
__global__ void __launch_bounds__(512) k_phaseB(const float* __restrict__ startT,
                                                const float* __restrict__ endT) {
    __shared__ float A[NCH * 81];        // 10368 B
    __shared__ float Bb[(NCH / 2) * 81]; // 5184 B
    __shared__ float sa[Ln], see[Ln];
    __shared__ float slog;
    int b = blockIdx.x, tid = threadIdx.x;

    const float* gm = g_M + (size_t)b * NCH * 81;
    for (int i = tid; i < NCH * 81; i += 512) A[i] = gm[i];
    if (tid < 32) {
        float lg = g_logs[b * NCH + tid];
#pragma unroll
        for (int o = 16; o > 0; o >>= 1) lg += __shfl_xor_sync(0xffffffffu, lg, o);
        if (tid == 0) slog = lg;
    }
    if (tid >= 64 && tid < 64 + Ln)
        sa[tid - 64] = __expf(startT[tid - 64] + g_em[(size_t)b * Sn * Ln + (tid - 64)]);
    if (tid >= 96 && tid < 96 + Ln) see[tid - 96] = __expf(endT[tid - 96]);
    __syncthreads();

    float* src = A;
    float* dst = Bb;
    for (int np = NCH / 2; np >= 1; np >>= 1) {
        for (int e = tid; e < np * 81; e += 512) {
            int p = e / 81, r = e % 81, i = r / 9, j = r % 9;
            const float* Am = src + 2 * p * 81;
            const float* Bm = src + (2 * p + 1) * 81;
            float s = 0.f;
#pragma unroll
            for (int k = 0; k < 9; k++) s += Am[i * 9 + k] * Bm[k * 9 + j];
            dst[e] = s * (1.f / 9.f);
        }
        __syncthreads();
        float* t = src; src = dst; dst = t;
    }
    // final matrix F in src[0..81)
    if (tid < 32) {
        float t = 0.f;
        for (int e = tid; e < 81; e += 32) {
            int i = e / 9, j = e % 9;
            t += sa[i] * src[e] * see[j];
        }
#pragma unroll
        for (int o = 16; o > 0; o >>= 1) t += __shfl_xor_sync(0xffffffffu, t, o);
        if (tid == 0)
            atomicAdd(&g_acc, __logf(t) + slog + 68.11396194f);  // 31*ln(9)
    }
}

__global__ void k_out(float* __restrict__ out) { out[0] = g_acc; }

// ---------------------------------------------------------------------------
extern "C" void kernel_launch(void* const* d_in, const int* in_sizes, int n_in,
                              void* d_out, int out_size) {
    const float* x      = (const float*)d_in[0];   // (64,512,1024) f32
    const int*   tags   = (const int*)d_in[1];     // (64,512) i32
    const int*   mask   = (const int*)d_in[2];     // (64,512) bool -> i32
    const float* W      = (const float*)d_in[3];   // (9,1024) f32
    const float* bias   = (const float*)d_in[4];   // (9,)
    const float* startT = (const float*)d_in[5];   // (9,)
    const float* endT   = (const float*)d_in[6];   // (9,)
    const float* T      = (const float*)d_in[7];   // (9,9)

    k_gemm  <<<128, 256>>>(x, W, bias);
    k_score <<<64, 512>>>(tags, mask, startT, endT, T);
    k_chunk <<<512, 128>>>(mask, T);
    k_phaseB<<<64, 512>>>(startT, endT);
    k_out   <<<1, 1>>>((float*)d_out);
}

// round 13
// speedup vs baseline: 1.4818x; 1.0503x over previous
#include <cuda_runtime.h>
#include <math.h>

#define Bn 64
#define Sn 512
#define Hn 1024
#define Ln 9
#define NCH 32
#define CH 16

// Scratch (no allocations allowed) — all plain stores, no global atomics on values
__device__ float g_em[(size_t)Bn * Sn * Ln];   // emissions (log domain), 1.18 MB
__device__ float g_part[128];                  // per-gemm-block score partials
__device__ float g_batch[Bn];                  // per-batch logZ - endterm
__device__ int   g_cnt;                        // k_crf arrival counter (reset by k_gemm)

#define FMA2(acc, a, b) asm("fma.rn.f32x2 %0, %1, %2, %0;" : "+l"(acc) : "l"(a), "l"(b))

// ---------------------------------------------------------------------------
// Kernel 1: emissions GEMM + numerator score fused in the epilogue.
// 128 blocks x 256 thr; warp = 8 row-slots x 4-lane quads; 4 rows/lane with
// W float4 reuse and packed f32x2 FMA. Score terms use the emission values
// still in registers; per-block partial -> g_part[blk] (no atomics).
// ---------------------------------------------------------------------------
__global__ void __launch_bounds__(256) k_gemm(const float* __restrict__ x,
                                              const float* __restrict__ W,
                                              const float* __restrict__ bias,
                                              const int* __restrict__ tags,
                                              const int* __restrict__ mask,
                                              const float* __restrict__ startT,
                                              const float* __restrict__ T) {
    __shared__ float sW[Ln * Hn];
    __shared__ float sb[Ln];
    __shared__ float sT[81];
    __shared__ float sst[Ln];
    __shared__ float sred[8];
    int tid = threadIdx.x;
    if (blockIdx.x == 0 && tid == 0) g_cnt = 0;   // safe: k_crf runs after this kernel
    for (int i = tid; i < Ln * Hn / 4; i += 256)
        ((float4*)sW)[i] = ((const float4*)W)[i];
    if (tid < Ln) sb[tid] = bias[tid];
    if (tid >= 32 && tid < 32 + 81) sT[tid - 32] = T[tid - 32];
    if (tid >= 128 && tid < 128 + Ln) sst[tid - 128] = startT[tid - 128];
    __syncthreads();

    int lane = tid & 31;
    int warp = tid >> 5;                     // 0..7
    int rw = lane >> 2;                      // row slot 0..7
    int quad = lane & 3;                     // k-slice
    size_t row0 = (size_t)blockIdx.x * 256 + warp * 32 + rw * 4;

    const ulonglong2* xr = (const ulonglong2*)(x + row0 * Hn);  // 256 u2 per row

    unsigned long long acc[4][Ln];
#pragma unroll
    for (int r = 0; r < 4; r++)
#pragma unroll
        for (int l = 0; l < Ln; l++) acc[r][l] = 0ull;

#pragma unroll 2
    for (int j = 0; j < 64; j++) {
        int kv = quad + j * 4;               // float4 index 0..255
        ulonglong2 x0 = xr[kv];
        ulonglong2 x1 = xr[256 + kv];
        ulonglong2 x2 = xr[512 + kv];
        ulonglong2 x3 = xr[768 + kv];
#pragma unroll
        for (int l = 0; l < Ln; l++) {
            ulonglong2 wv = ((const ulonglong2*)(sW + l * Hn))[kv];
            FMA2(acc[0][l], x0.x, wv.x); FMA2(acc[0][l], x0.y, wv.y);
            FMA2(acc[1][l], x1.x, wv.x); FMA2(acc[1][l], x1.y, wv.y);
            FMA2(acc[2][l], x2.x, wv.x); FMA2(acc[2][l], x2.y, wv.y);
            FMA2(acc[3][l], x3.x, wv.x); FMA2(acc[3][l], x3.y, wv.y);
        }
    }

    // per-row tag/mask metadata (quad==0 lanes own the rows)
    int tg[4], pv[4], mk4[4];
    if (quad == 0) {
#pragma unroll
        for (int r = 0; r < 4; r++) {
            size_t row = row0 + r;
            int s = (int)(row & (Sn - 1));
            tg[r] = tags[row];
            mk4[r] = mask[row];
            pv[r] = (s > 0) ? tags[row - 1] : 0;
        }
    }

    float score = 0.f;
#pragma unroll
    for (int r = 0; r < 4; r++) {
        float ev = 0.f;
#pragma unroll
        for (int l = 0; l < Ln; l++) {
            float lo, hi;
            asm("mov.b64 {%0, %1}, %2;" : "=f"(lo), "=f"(hi) : "l"(acc[r][l]));
            float v = lo + hi;
            v += __shfl_xor_sync(0xffffffffu, v, 1);
            v += __shfl_xor_sync(0xffffffffu, v, 2);
            if (quad == 0) {
                float vf = v + sb[l];
                g_em[(row0 + r) * Ln + l] = vf;
                if (l == tg[r]) ev = vf;
            }
        }
        if (quad == 0) {
            int s = (int)((row0 + r) & (Sn - 1));
            if (s == 0)          score += sst[tg[r]] + ev;
            else if (mk4[r] != 0) score += sT[pv[r] * 9 + tg[r]] + ev;
        }
    }
    // block reduce (quad!=0 lanes contribute 0)
#pragma unroll
    for (int o = 16; o > 0; o >>= 1) score += __shfl_xor_sync(0xffffffffu, score, o);
    if (lane == 0) sred[warp] = score;
    __syncthreads();
    if (warp == 0) {
        float t = (lane < 8) ? sred[lane] : 0.f;
#pragma unroll
        for (int o = 4; o > 0; o >>= 1) t += __shfl_xor_sync(0xffffffffu, t, o);
        if (lane == 0) g_part[blockIdx.x] = t;
    }
}

// ---------------------------------------------------------------------------
// Kernel 2: full CRF partition function per batch, fused.
// Block = 1024 thr = 32 warps; warp w folds chunk w (CH=16 steps) in the EXP
// domain, normalizes (max=1, log kept), then a 5-level in-block tree combines
// the 32 matrices (each product scaled 1/9; entries stay bounded). logZ and
// the end-transition term produce g_batch[b]. The last-arriving block sums
// g_batch - g_part and writes d_out.
// ---------------------------------------------------------------------------
__global__ void __launch_bounds__(1024, 1) k_crf(const int* __restrict__ tags,
                                                 const int* __restrict__ mask,
                                                 const float* __restrict__ startT,
                                                 const float* __restrict__ endT,
                                                 const float* __restrict__ T,
                                                 float* __restrict__ out) {
    __shared__ float sE[32][2][81];      // 20736 B ping-pong scan buffers
    __shared__ float bufA[32 * 81];      // 10368 B tree buffer
    __shared__ float bufB[16 * 81];      //  5184 B tree buffer
    __shared__ float sTe[81];            // exp(T)
    __shared__ float slog[32];
    __shared__ float sa[Ln], sev[Ln];
    __shared__ int scnt;
    __shared__ int sflag;
    __shared__ float sdot, sls, sendt;
    __shared__ float sred2[32];

    int b = blockIdx.x;
    int tid = threadIdx.x;
    int lane = tid & 31, w = tid >> 5;

    if (tid == 0) { scnt = 0; sflag = 0; }
    if (tid < 81) sTe[tid] = __expf(T[tid]);
    __syncthreads();

    // ---- per-warp chunk scan (chunk c = w) ----
    int e0 = lane, e1 = lane + 32, e2 = lane + 64;
    bool act2 = (e2 < 81);
    int i0 = e0 / 9, j0 = e0 % 9;
    int i1 = e1 / 9, j1 = e1 % 9;
    int i2 = act2 ? e2 / 9 : 0, j2 = act2 ? e2 % 9 : 0;

    float eT0[9], eT1[9], eT2[9];
#pragma unroll
    for (int k = 0; k < 9; k++) {
        eT0[k] = sTe[k * 9 + j0];
        eT1[k] = sTe[k * 9 + j1];
        eT2[k] = act2 ? sTe[k * 9 + j2] : 0.f;
    }
    float eTd0 = sTe[i0 * 9 + j0];
    float eTd1 = sTe[i1 * 9 + j1];
    float eTd2 = act2 ? sTe[i2 * 9 + j2] : 0.f;

    const float* emb = g_em + (size_t)b * Sn * Ln;
    const int* mb = mask + b * Sn;
    int s0 = 1 + w * CH;
    int send = min(Sn, s0 + CH);

    int mnext = mb[s0];
    float q0 = emb[s0 * 9 + j0];
    float q1 = emb[s0 * 9 + j1];
    float q2 = act2 ? emb[s0 * 9 + j2] : 0.f;

    int cur = 0;
    bool have = false;
    for (int s = s0; s < send; s++) {
        int mcur = mnext;
        float a0 = q0, a1 = q1, a2 = q2;
        if (s + 1 < send) {
            mnext = mb[s + 1];
            q0 = emb[(s + 1) * 9 + j0];
            q1 = emb[(s + 1) * 9 + j1];
            q2 = act2 ? emb[(s + 1) * 9 + j2] : 0.f;
        }
        if (mcur == 0) continue;         // uniform per warp
        float x0 = __expf(a0);
        float x1 = __expf(a1);
        float x2 = act2 ? __expf(a2) : 0.f;
        if (!have) {
            float* E = sE[w][cur];
            E[e0] = eTd0 * x0;
            E[e1] = eTd1 * x1;
            if (act2) E[e2] = eTd2 * x2;
            have = true;
            __syncwarp();
        } else {
            const float* E = sE[w][cur];
            float* En = sE[w][cur ^ 1];
            float r0 = 0.f, r1 = 0.f, r2 = 0.f;
#pragma unroll
            for (int k = 0; k < 9; k++) {
                r0 += E[i0 * 9 + k] * eT0[k];
                r1 += E[i1 * 9 + k] * eT1[k];
                if (act2) r2 += E[i2 * 9 + k] * eT2[k];
            }
            En[e0] = r0 * x0;
            En[e1] = r1 * x1;
            if (act2) En[e2] = r2 * x2;
            cur ^= 1;
            __syncwarp();
        }
    }

    // normalize chunk matrix into bufA, keep log(max)
    float* outm = bufA + w * 81;
    if (have) {
        const float* E = sE[w][cur];
        float v0 = E[e0], v1 = E[e1], v2 = act2 ? E[e2] : 0.f;
        float m = fmaxf(fmaxf(v0, v1), v2);
        m = fmaxf(m, __shfl_xor_sync(0xffffffffu, m, 1));
        m = fmaxf(m, __shfl_xor_sync(0xffffffffu, m, 2));
        m = fmaxf(m, __shfl_xor_sync(0xffffffffu, m, 4));
        m = fmaxf(m, __shfl_xor_sync(0xffffffffu, m, 8));
        m = fmaxf(m, __shfl_xor_sync(0xffffffffu, m, 16));
        m = fmaxf(m, 1e-35f);
        float rcp = 1.f / m;
        outm[e0] = v0 * rcp; outm[e1] = v1 * rcp; if (act2) outm[e2] = v2 * rcp;
        if (lane == 0) slog[w] = __logf(m);
    } else {                             // exact identity (chunk fully masked)
        outm[e0] = (i0 == j0) ? 1.f : 0.f;
        outm[e1] = (i1 == j1) ? 1.f : 0.f;
        if (act2) outm[e2] = (i2 == j2) ? 1.f : 0.f;
        if (lane == 0) slog[w] = 0.f;
    }

    // mask popcount (warps 0..15 cover s=0..511), alpha0/end vectors
    if (tid < Sn) {
        int mk = (mb[tid] != 0);
        int cnt = __popc(__ballot_sync(0xffffffffu, mk));
        if (lane == 0) atomicAdd(&scnt, cnt);
    }
    if (tid >= 512 && tid < 512 + Ln)
        sa[tid - 512] = __expf(startT[tid - 512] + emb[tid - 512]);
    if (tid >= 544 && tid < 544 + Ln)
        sev[tid - 544] = __expf(endT[tid - 544]);
    __syncthreads();

    // end-transition term (scnt final now)
    if (tid == 0) {
        int cc = max(scnt, 1);
        sendt = endT[tags[b * Sn + cc - 1]];
    }

    // ---- 5-level tree: 32 -> 1 matrices, each product scaled by 1/9 ----
    float* src = bufA;
    float* dst = bufB;
    for (int np = 16; np >= 1; np >>= 1) {
        for (int e = tid; e < np * 81; e += 1024) {
            int p = e / 81, r = e % 81, i = r / 9, j = r % 9;
            const float* Am = src + 2 * p * 81;
            const float* Bm = src + (2 * p + 1) * 81;
            float s = 0.f;
#pragma unroll
            for (int k = 0; k < 9; k++) s += Am[i * 9 + k] * Bm[k * 9 + j];
            dst[e] = s * (1.f / 9.f);
        }
        __syncthreads();
        float* t = src; src = dst; dst = t;
    }
    // final matrix F in src[0..81)

    if (w == 0) {
        // dot = a0^T F e_end
        float t = sa[i0] * src[e0] * sev[j0]
                + sa[i1] * src[e1] * sev[j1]
                + (act2 ? sa[i2] * src[e2] * sev[j2] : 0.f);
#pragma unroll
        for (int o = 16; o > 0; o >>= 1) t += __shfl_xor_sync(0xffffffffu, t, o);
        // sum of chunk log-offsets
        float lg = slog[lane];
#pragma unroll
        for (int o = 16; o > 0; o >>= 1) lg += __shfl_xor_sync(0xffffffffu, lg, o);
        if (lane == 0) {
            g_batch[b] = __logf(t) + 68.11396194f /*31*ln9*/ + lg - sendt;
            __threadfence();
            int old = atomicAdd(&g_cnt, 1);
            if (old == Bn - 1) sflag = 1;
        }
    }
    __syncthreads();

    // last-arriving block computes the final scalar and writes d_out
    if (sflag) {
        float v = 0.f;
        if (tid < Bn) v = g_batch[tid];
        else if (tid < Bn + 128) v = -g_part[tid - Bn];
#pragma unroll
        for (int o = 16; o > 0; o >>= 1) v += __shfl_xor_sync(0xffffffffu, v, o);
        if (lane == 0) sred2[w] = v;
        __syncthreads();
        if (w == 0) {
            float t = sred2[lane];   // 32 partials (warps >=6 contributed 0)
#pragma unroll
            for (int o = 16; o > 0; o >>= 1) t += __shfl_xor_sync(0xffffffffu, t, o);
            if (lane == 0) out[0] = t;
        }
    }
}

// ---------------------------------------------------------------------------
extern "C" void kernel_launch(void* const* d_in, const int* in_sizes, int n_in,
                              void* d_out, int out_size) {
    const float* x      = (const float*)d_in[0];   // (64,512,1024) f32
    const int*   tags   = (const int*)d_in[1];     // (64,512) i32
    const int*   mask   = (const int*)d_in[2];     // (64,512) bool -> i32
    const float* W      = (const float*)d_in[3];   // (9,1024) f32
    const float* bias   = (const float*)d_in[4];   // (9,)
    const float* startT = (const float*)d_in[5];   // (9,)
    const float* endT   = (const float*)d_in[6];   // (9,)
    const float* T      = (const float*)d_in[7];   // (9,9)

    k_gemm<<<128, 256>>>(x, W, bias, tags, mask, startT, T);
    k_crf <<<64, 1024>>>(tags, mask, startT, endT, T, (float*)d_out);
}